// round 16
// baseline (speedup 1.0000x reference)
// CapsuleLayer r16 — capsB prefetch depth 3 pairs (6 rows resident).
#include <cuda_runtime.h>
#include <cuda_fp16.h>

#define N_B 32
#define N_N 2048
#define N_D 16
#define N_C 64
#define N_E 32
#define NPART 37
#define SBCE (N_B * N_C * N_E)   // 65536
#define U_ROW_U4 ((N_C * N_E) / 8)   // one n-row of u in uint4 units = 256

typedef unsigned long long ull;

// Scratch (device globals; allocation-free kernel_launch)
// +6 rows padding: capsB 3-pair prefetch can touch rows up to ne+3.
__device__ __half g_u[(size_t)N_B * N_N * N_C * N_E + 6 * N_C * N_E];
__device__ float  g_partials[(size_t)NPART * SBCE];          // partial s sums
__device__ float  g_vsum[SBCE];                              // sum of v_j so far

// ---- packed f32x2 helpers (sm_100+) ----
__device__ __forceinline__ ull ffma2(ull a, ull b, ull c) {
    ull d;
    asm("fma.rn.f32x2 %0, %1, %2, %3;" : "=l"(d) : "l"(a), "l"(b), "l"(c));
    return d;
}
__device__ __forceinline__ ull fadd2(ull a, ull b) {
    ull d;
    asm("add.rn.f32x2 %0, %1, %2;" : "=l"(d) : "l"(a), "l"(b));
    return d;
}
__device__ __forceinline__ ull fpack2(float lo, float hi) {
    ull d;
    asm("mov.b64 %0, {%1, %2};" : "=l"(d) : "f"(lo), "f"(hi));
    return d;
}
__device__ __forceinline__ float2 funpack2(ull v) {
    float2 f;
    asm("mov.b64 {%0, %1}, %2;" : "=f"(f.x), "=f"(f.y) : "l"(v));
    return f;
}
// half2 (as u32) -> packed f32x2 (as ull)
__device__ __forceinline__ ull h2f2(unsigned h) {
    __half2 hh = reinterpret_cast<__half2&>(h);
    float2 f = __half22float2(hh);
    ull r;
    asm("mov.b64 %0, {%1, %2};" : "=l"(r) : "f"(f.x), "f"(f.y));
    return r;
}

// ---- cp.async helpers (capsA only) ----
__device__ __forceinline__ void cp16(void* smem_dst, const void* gmem_src) {
    unsigned s = (unsigned)__cvta_generic_to_shared(smem_dst);
    asm volatile("cp.async.cg.shared.global [%0], [%1], 16;" :: "r"(s), "l"(gmem_src));
}
__device__ __forceinline__ void cp_commit() {
    asm volatile("cp.async.commit_group;");
}
__device__ __forceinline__ void cp_wait3() {
    asm volatile("cp.async.wait_group 3;" ::: "memory");
}

// capsA dynamic smem: 4-deep ring.  Ws[4][4096] floats + xs[4][512] floats
#define CAPSA_WS_FLOATS (4 * 4096)
#define CAPSA_XS_FLOATS (4 * 512)
#define CAPSA_SMEM_BYTES ((CAPSA_WS_FLOATS + CAPSA_XS_FLOATS) * 4)

// ---------------------------------------------------------------------------
// Kernel A (unchanged — measured near its DRAM roofline, ~111us):
// u = x*W + B via packed f32x2 FFMA, store u fp16, accumulate sum_n u
// ---------------------------------------------------------------------------
__global__ __launch_bounds__(256, 2)
void capsA(const float* __restrict__ x, const float* __restrict__ W,
           const float* __restrict__ Bv)
{
    extern __shared__ float smem[];
    float* Wsm = smem;                        // [4][4096]
    float* xsm = smem + CAPSA_WS_FLOATS;      // [4][512]

    const int tid = threadIdx.x;
    const int cc  = blockIdx.x;
    const int nb  = blockIdx.y;
    const int c0  = cc * 8;
    const int ns  = (nb * N_N) / NPART;
    const int ne  = ((nb + 1) * N_N) / NPART;

    const int lane    = tid & 31;
    const int bq      = tid >> 5;
    const int c_local = lane >> 2;
    const int a       = lane & 3;
    const int swz4    = c_local & 7;
    const int c       = c0 + c_local;
    const int e_base  = 8 * a;

    ull Bv2[4];
    #pragma unroll
    for (int j = 0; j < 4; j++)
        Bv2[j] = fpack2(Bv[c * N_E + e_base + 2 * j],
                        Bv[c * N_E + e_base + 2 * j + 1]);

    ull sacc[4][4];
    #pragma unroll
    for (int i = 0; i < 4; i++)
        #pragma unroll
        for (int j = 0; j < 4; j++) sacc[i][j] = 0ull;

    auto stage = [&](int n, int buf) {
        const float* Wn = W + (size_t)n * (N_C * N_D * N_E) + (size_t)c0 * (N_D * N_E);
        float* Wb = Wsm + buf * 4096;
        #pragma unroll
        for (int k = 0; k < 4; k++) {
            int q = tid + 256 * k;
            int p = q * 4;
            int cl = p >> 9;
            int d  = (p >> 5) & 15;
            int e4 = (p & 31) >> 2;
            float* dst = &Wb[cl * 512 + d * 32 + ((e4 ^ (cl & 7)) << 2)];
            cp16(dst, Wn + p);
        }
        if (tid < 128) {
            int b = tid >> 2, dq = tid & 3;
            cp16(&xsm[buf * 512 + b * N_D + dq * 4],
                 x + ((size_t)b * N_N + n) * N_D + dq * 4);
        }
        cp_commit();
    };

    stage(ns, 0);
    if (ns + 1 < ne) stage(ns + 1, 1); else cp_commit();
    if (ns + 2 < ne) stage(ns + 2, 2); else cp_commit();

    for (int n = ns; n < ne; n++) {
        int r   = n - ns;
        int buf = r & 3;
        int nxt = n + 3;
        if (nxt < ne) stage(nxt, (r + 3) & 3); else cp_commit();
        cp_wait3();
        __syncthreads();

        ull uacc[4][4];
        #pragma unroll
        for (int i = 0; i < 4; i++)
            #pragma unroll
            for (int j = 0; j < 4; j++) uacc[i][j] = 0ull;

        const float* Wrow = Wsm + buf * 4096 + c_local * 512;
        const float* xrow = xsm + buf * 512;
        #pragma unroll
        for (int d = 0; d < N_D; d++) {
            ull xv[4];
            #pragma unroll
            for (int i = 0; i < 4; i++) {
                float xval = xrow[(bq * 4 + i) * N_D + d];
                xv[i] = fpack2(xval, xval);
            }
            int o0 = (((2 * a + 0) ^ swz4) << 2) + d * 32;
            int o1 = (((2 * a + 1) ^ swz4) << 2) + d * 32;
            ulonglong2 w01 = *reinterpret_cast<const ulonglong2*>(Wrow + o0);
            ulonglong2 w23 = *reinterpret_cast<const ulonglong2*>(Wrow + o1);
            ull wv[4] = { w01.x, w01.y, w23.x, w23.y };
            #pragma unroll
            for (int i = 0; i < 4; i++)
                #pragma unroll
                for (int j = 0; j < 4; j++)
                    uacc[i][j] = ffma2(xv[i], wv[j], uacc[i][j]);
        }

        #pragma unroll
        for (int i = 0; i < 4; i++) {
            int b = bq * 4 + i;
            unsigned h[4];
            #pragma unroll
            for (int j = 0; j < 4; j++) {
                ull t = fadd2(uacc[i][j], Bv2[j]);
                sacc[i][j] = fadd2(sacc[i][j], t);
                float2 tf = funpack2(t);
                __half2 hh = __floats2half2_rn(tf.x, tf.y);
                h[j] = reinterpret_cast<unsigned&>(hh);
            }
            size_t uoff = (((size_t)b * N_N + n) * N_C + c) * N_E + e_base;
            *reinterpret_cast<uint4*>(&g_u[uoff]) = make_uint4(h[0], h[1], h[2], h[3]);
        }
        __syncthreads();
    }

    #pragma unroll
    for (int i = 0; i < 4; i++) {
        int b = bq * 4 + i;
        ull* dst = reinterpret_cast<ull*>(
            &g_partials[(size_t)nb * SBCE + ((size_t)b * N_C + c) * N_E + e_base]);
        *reinterpret_cast<ulonglong2*>(dst)     = make_ulonglong2(sacc[i][0], sacc[i][1]);
        *reinterpret_cast<ulonglong2*>(dst + 2) = make_ulonglong2(sacc[i][2], sacc[i][3]);
    }
}

// ---------------------------------------------------------------------------
// Kernel B: logits = u.vsum, softmax_c, s += coup*u.
// Unroll-2 (2 n per barrier, parity wsum) + 3-pair register prefetch ring
// (6 rows resident -> ~6 LDG.128 in flight per lane, hides DRAM latency).
// ---------------------------------------------------------------------------
__global__ __launch_bounds__(256, 4)
void capsB()
{
    __shared__ __align__(16) float wsum[2][2][8];   // [parity][which n][warp]

    const int tid  = threadIdx.x;
    const int b    = blockIdx.x;
    const int nb   = blockIdx.y;
    const int ns   = (nb * N_N) / NPART;
    const int ne   = ((nb + 1) * N_N) / NPART;
    const int lane = tid & 31;
    const int wid  = tid >> 5;

    // vsum for this (c, 8e), packed f32x2
    ull vs2[4];
    {
        const float4* vp = reinterpret_cast<const float4*>(
            g_vsum + (size_t)b * (N_C * N_E) + tid * 8);
        float4 v0 = vp[0], v1 = vp[1];
        vs2[0] = fpack2(v0.x, v0.y);
        vs2[1] = fpack2(v0.z, v0.w);
        vs2[2] = fpack2(v1.x, v1.y);
        vs2[3] = fpack2(v1.z, v1.w);
    }
    ull sacc2[4] = { 0ull, 0ull, 0ull, 0ull };

    const uint4* __restrict__ up = reinterpret_cast<const uint4*>(
        g_u + (size_t)b * N_N * (N_C * N_E) + tid * 8);

    const int cnt    = ne - ns;          // 55 or 56
    const int npairs = cnt >> 1;

    // 3 pairs resident: v0,v1 = current pair; v2,v3 = +1; v4,v5 = +2
    uint4 v0 = up[(size_t)(ns + 0) * U_ROW_U4];
    uint4 v1 = up[(size_t)(ns + 1) * U_ROW_U4];
    uint4 v2 = up[(size_t)(ns + 2) * U_ROW_U4];
    uint4 v3 = up[(size_t)(ns + 3) * U_ROW_U4];

    int p = 0;
    int n = ns;
    for (int it = 0; it < npairs; it++, n += 2, p ^= 1) {
        uint4 v4 = up[(size_t)(n + 4) * U_ROW_U4];   // +2 pairs ahead (padded)
        uint4 v5 = up[(size_t)(n + 5) * U_ROW_U4];

        ull a0 = h2f2(v0.x), a1 = h2f2(v0.y), a2 = h2f2(v0.z), a3 = h2f2(v0.w);
        ull b0 = h2f2(v1.x), b1 = h2f2(v1.y), b2 = h2f2(v1.z), b3 = h2f2(v1.w);

        ull accA = ffma2(a0, vs2[0], 0ull);
        ull accB = ffma2(b0, vs2[0], 0ull);
        accA = ffma2(a1, vs2[1], accA);
        accB = ffma2(b1, vs2[1], accB);
        accA = ffma2(a2, vs2[2], accA);
        accB = ffma2(b2, vs2[2], accB);
        accA = ffma2(a3, vs2[3], accA);
        accB = ffma2(b3, vs2[3], accB);
        float2 fA = funpack2(accA);
        float2 fB = funpack2(accB);
        float lpA = fA.x + fA.y;
        float lpB = fB.x + fB.y;
        lpA += __shfl_xor_sync(0xffffffffu, lpA, 1);
        lpB += __shfl_xor_sync(0xffffffffu, lpB, 1);
        lpA += __shfl_xor_sync(0xffffffffu, lpA, 2);
        lpB += __shfl_xor_sync(0xffffffffu, lpB, 2);

        float exA = __expf(lpA);
        float exB = __expf(lpB);
        float sA = exA, sB = exB;
        sA += __shfl_xor_sync(0xffffffffu, sA, 4);
        sB += __shfl_xor_sync(0xffffffffu, sB, 4);
        sA += __shfl_xor_sync(0xffffffffu, sA, 8);
        sB += __shfl_xor_sync(0xffffffffu, sB, 8);
        sA += __shfl_xor_sync(0xffffffffu, sA, 16);
        sB += __shfl_xor_sync(0xffffffffu, sB, 16);
        if (lane == 0) {
            wsum[p][0][wid] = sA;
            wsum[p][1][wid] = sB;
        }
        __syncthreads();

        const float4* wpA = reinterpret_cast<const float4*>(wsum[p][0]);
        const float4* wpB = reinterpret_cast<const float4*>(wsum[p][1]);
        float4 aA = wpA[0], bA = wpA[1];
        float4 aB = wpB[0], bB = wpB[1];
        float totA = ((aA.x + aA.y) + (aA.z + aA.w)) +
                     ((bA.x + bA.y) + (bA.z + bA.w));
        float totB = ((aB.x + aB.y) + (aB.z + aB.w)) +
                     ((bB.x + bB.y) + (bB.z + bB.w));
        float coupA = __fdividef(exA, totA);
        float coupB = __fdividef(exB, totB);

        ull cA = fpack2(coupA, coupA);
        ull cB = fpack2(coupB, coupB);
        sacc2[0] = ffma2(cA, a0, sacc2[0]);
        sacc2[1] = ffma2(cA, a1, sacc2[1]);
        sacc2[2] = ffma2(cA, a2, sacc2[2]);
        sacc2[3] = ffma2(cA, a3, sacc2[3]);
        sacc2[0] = ffma2(cB, b0, sacc2[0]);
        sacc2[1] = ffma2(cB, b1, sacc2[1]);
        sacc2[2] = ffma2(cB, b2, sacc2[2]);
        sacc2[3] = ffma2(cB, b3, sacc2[3]);

        v0 = v2; v1 = v3; v2 = v4; v3 = v5;
    }

    if (cnt & 1) {
        // tail n = ns + cnt - 1; its row sits in v0 after the shifts
        ull a0 = h2f2(v0.x), a1 = h2f2(v0.y), a2 = h2f2(v0.z), a3 = h2f2(v0.w);
        ull acc = ffma2(a0, vs2[0], 0ull);
        acc = ffma2(a1, vs2[1], acc);
        acc = ffma2(a2, vs2[2], acc);
        acc = ffma2(a3, vs2[3], acc);
        float2 f = funpack2(acc);
        float lp = f.x + f.y;
        lp += __shfl_xor_sync(0xffffffffu, lp, 1);
        lp += __shfl_xor_sync(0xffffffffu, lp, 2);
        float ex = __expf(lp);
        float s = ex;
        s += __shfl_xor_sync(0xffffffffu, s, 4);
        s += __shfl_xor_sync(0xffffffffu, s, 8);
        s += __shfl_xor_sync(0xffffffffu, s, 16);
        if (lane == 0) wsum[p][0][wid] = s;
        __syncthreads();
        const float4* wp = reinterpret_cast<const float4*>(wsum[p][0]);
        float4 wa = wp[0], wb = wp[1];
        float tot = ((wa.x + wa.y) + (wa.z + wa.w)) +
                    ((wb.x + wb.y) + (wb.z + wb.w));
        float coup = __fdividef(ex, tot);
        ull c2 = fpack2(coup, coup);
        sacc2[0] = ffma2(c2, a0, sacc2[0]);
        sacc2[1] = ffma2(c2, a1, sacc2[1]);
        sacc2[2] = ffma2(c2, a2, sacc2[2]);
        sacc2[3] = ffma2(c2, a3, sacc2[3]);
    }

    // write partials (32B contiguous per thread)
    ull* dst = reinterpret_cast<ull*>(
        &g_partials[(size_t)nb * SBCE + (size_t)b * (N_C * N_E) + tid * 8]);
    *reinterpret_cast<ulonglong2*>(dst)     = make_ulonglong2(sacc2[0], sacc2[1]);
    *reinterpret_cast<ulonglong2*>(dst + 2) = make_ulonglong2(sacc2[2], sacc2[3]);
}

// ---------------------------------------------------------------------------
// reduce partials (round-5 proven version): 2048 blocks x 32 threads
// ---------------------------------------------------------------------------
__global__ void reduce_squash(float scale, int overwrite, float* __restrict__ out)
{
    int bc = blockIdx.x;     // b*64 + c
    int e  = threadIdx.x;
    size_t idx = (size_t)bc * N_E + e;
    float s = 0.0f;
    #pragma unroll
    for (int p = 0; p < NPART; p++)
        s += g_partials[(size_t)p * SBCE + idx];
    s *= scale;
    float nsq = s * s;
    #pragma unroll
    for (int m = 16; m >= 1; m >>= 1)
        nsq += __shfl_xor_sync(0xffffffffu, nsq, m);
    float sc = nsq / ((1.0f + nsq) * sqrtf(nsq + 1e-9f));
    float v = sc * s;
    if (overwrite) g_vsum[idx] = v;
    else           g_vsum[idx] += v;
    if (out) out[idx] = v;
}

// ---------------------------------------------------------------------------
extern "C" void kernel_launch(void* const* d_in, const int* in_sizes, int n_in,
                              void* d_out, int out_size)
{
    const float* x  = (const float*)d_in[0];
    const float* W  = (const float*)d_in[1];
    const float* Bv = (const float*)d_in[2];
    float* out = (float*)d_out;

    cudaFuncSetAttribute(capsA, cudaFuncAttributeMaxDynamicSharedMemorySize,
                         CAPSA_SMEM_BYTES);

    dim3 gA(8, NPART);
    dim3 gB(N_B, NPART);

    capsA<<<gA, 256, CAPSA_SMEM_BYTES>>>(x, W, Bv);
    reduce_squash<<<N_B * N_C, 32>>>(1.0f / 64.0f, 1, nullptr);   // v1 -> vsum
    capsB<<<gB, 256>>>();
    reduce_squash<<<N_B * N_C, 32>>>(1.0f, 0, nullptr);           // vsum += v2
    capsB<<<gB, 256>>>();
    reduce_squash<<<N_B * N_C, 32>>>(1.0f, 0, out);
}

// round 17
// speedup vs baseline: 1.0512x; 1.0512x over previous
// CapsuleLayer r17 — capsB reverted to r15 (depth-2, unroll-2, best 244us);
// reduce_squash regridded to 512x128 (same per-element math, better occupancy).
#include <cuda_runtime.h>
#include <cuda_fp16.h>

#define N_B 32
#define N_N 2048
#define N_D 16
#define N_C 64
#define N_E 32
#define NPART 37
#define SBCE (N_B * N_C * N_E)   // 65536
#define U_ROW_U4 ((N_C * N_E) / 8)   // one n-row of u in uint4 units = 256

typedef unsigned long long ull;

// Scratch (device globals; allocation-free kernel_launch)
// +4 rows padding: capsB pair-prefetch can touch rows ne..ne+1 past the last slab.
__device__ __half g_u[(size_t)N_B * N_N * N_C * N_E + 4 * N_C * N_E];
__device__ float  g_partials[(size_t)NPART * SBCE];          // partial s sums
__device__ float  g_vsum[SBCE];                              // sum of v_j so far

// ---- packed f32x2 helpers (sm_100+) ----
__device__ __forceinline__ ull ffma2(ull a, ull b, ull c) {
    ull d;
    asm("fma.rn.f32x2 %0, %1, %2, %3;" : "=l"(d) : "l"(a), "l"(b), "l"(c));
    return d;
}
__device__ __forceinline__ ull fadd2(ull a, ull b) {
    ull d;
    asm("add.rn.f32x2 %0, %1, %2;" : "=l"(d) : "l"(a), "l"(b));
    return d;
}
__device__ __forceinline__ ull fpack2(float lo, float hi) {
    ull d;
    asm("mov.b64 %0, {%1, %2};" : "=l"(d) : "f"(lo), "f"(hi));
    return d;
}
__device__ __forceinline__ float2 funpack2(ull v) {
    float2 f;
    asm("mov.b64 {%0, %1}, %2;" : "=f"(f.x), "=f"(f.y) : "l"(v));
    return f;
}
// half2 (as u32) -> packed f32x2 (as ull)
__device__ __forceinline__ ull h2f2(unsigned h) {
    __half2 hh = reinterpret_cast<__half2&>(h);
    float2 f = __half22float2(hh);
    ull r;
    asm("mov.b64 %0, {%1, %2};" : "=l"(r) : "f"(f.x), "f"(f.y));
    return r;
}

// ---- cp.async helpers (capsA only) ----
__device__ __forceinline__ void cp16(void* smem_dst, const void* gmem_src) {
    unsigned s = (unsigned)__cvta_generic_to_shared(smem_dst);
    asm volatile("cp.async.cg.shared.global [%0], [%1], 16;" :: "r"(s), "l"(gmem_src));
}
__device__ __forceinline__ void cp_commit() {
    asm volatile("cp.async.commit_group;");
}
__device__ __forceinline__ void cp_wait3() {
    asm volatile("cp.async.wait_group 3;" ::: "memory");
}

// capsA dynamic smem: 4-deep ring.  Ws[4][4096] floats + xs[4][512] floats
#define CAPSA_WS_FLOATS (4 * 4096)
#define CAPSA_XS_FLOATS (4 * 512)
#define CAPSA_SMEM_BYTES ((CAPSA_WS_FLOATS + CAPSA_XS_FLOATS) * 4)

// ---------------------------------------------------------------------------
// Kernel A (unchanged — at/near its DRAM roofline):
// u = x*W + B via packed f32x2 FFMA, store u fp16, accumulate sum_n u
// ---------------------------------------------------------------------------
__global__ __launch_bounds__(256, 2)
void capsA(const float* __restrict__ x, const float* __restrict__ W,
           const float* __restrict__ Bv)
{
    extern __shared__ float smem[];
    float* Wsm = smem;                        // [4][4096]
    float* xsm = smem + CAPSA_WS_FLOATS;      // [4][512]

    const int tid = threadIdx.x;
    const int cc  = blockIdx.x;
    const int nb  = blockIdx.y;
    const int c0  = cc * 8;
    const int ns  = (nb * N_N) / NPART;
    const int ne  = ((nb + 1) * N_N) / NPART;

    const int lane    = tid & 31;
    const int bq      = tid >> 5;
    const int c_local = lane >> 2;
    const int a       = lane & 3;
    const int swz4    = c_local & 7;
    const int c       = c0 + c_local;
    const int e_base  = 8 * a;

    ull Bv2[4];
    #pragma unroll
    for (int j = 0; j < 4; j++)
        Bv2[j] = fpack2(Bv[c * N_E + e_base + 2 * j],
                        Bv[c * N_E + e_base + 2 * j + 1]);

    ull sacc[4][4];
    #pragma unroll
    for (int i = 0; i < 4; i++)
        #pragma unroll
        for (int j = 0; j < 4; j++) sacc[i][j] = 0ull;

    auto stage = [&](int n, int buf) {
        const float* Wn = W + (size_t)n * (N_C * N_D * N_E) + (size_t)c0 * (N_D * N_E);
        float* Wb = Wsm + buf * 4096;
        #pragma unroll
        for (int k = 0; k < 4; k++) {
            int q = tid + 256 * k;
            int p = q * 4;
            int cl = p >> 9;
            int d  = (p >> 5) & 15;
            int e4 = (p & 31) >> 2;
            float* dst = &Wb[cl * 512 + d * 32 + ((e4 ^ (cl & 7)) << 2)];
            cp16(dst, Wn + p);
        }
        if (tid < 128) {
            int b = tid >> 2, dq = tid & 3;
            cp16(&xsm[buf * 512 + b * N_D + dq * 4],
                 x + ((size_t)b * N_N + n) * N_D + dq * 4);
        }
        cp_commit();
    };

    stage(ns, 0);
    if (ns + 1 < ne) stage(ns + 1, 1); else cp_commit();
    if (ns + 2 < ne) stage(ns + 2, 2); else cp_commit();

    for (int n = ns; n < ne; n++) {
        int r   = n - ns;
        int buf = r & 3;
        int nxt = n + 3;
        if (nxt < ne) stage(nxt, (r + 3) & 3); else cp_commit();
        cp_wait3();
        __syncthreads();

        ull uacc[4][4];
        #pragma unroll
        for (int i = 0; i < 4; i++)
            #pragma unroll
            for (int j = 0; j < 4; j++) uacc[i][j] = 0ull;

        const float* Wrow = Wsm + buf * 4096 + c_local * 512;
        const float* xrow = xsm + buf * 512;
        #pragma unroll
        for (int d = 0; d < N_D; d++) {
            ull xv[4];
            #pragma unroll
            for (int i = 0; i < 4; i++) {
                float xval = xrow[(bq * 4 + i) * N_D + d];
                xv[i] = fpack2(xval, xval);
            }
            int o0 = (((2 * a + 0) ^ swz4) << 2) + d * 32;
            int o1 = (((2 * a + 1) ^ swz4) << 2) + d * 32;
            ulonglong2 w01 = *reinterpret_cast<const ulonglong2*>(Wrow + o0);
            ulonglong2 w23 = *reinterpret_cast<const ulonglong2*>(Wrow + o1);
            ull wv[4] = { w01.x, w01.y, w23.x, w23.y };
            #pragma unroll
            for (int i = 0; i < 4; i++)
                #pragma unroll
                for (int j = 0; j < 4; j++)
                    uacc[i][j] = ffma2(xv[i], wv[j], uacc[i][j]);
        }

        #pragma unroll
        for (int i = 0; i < 4; i++) {
            int b = bq * 4 + i;
            unsigned h[4];
            #pragma unroll
            for (int j = 0; j < 4; j++) {
                ull t = fadd2(uacc[i][j], Bv2[j]);
                sacc[i][j] = fadd2(sacc[i][j], t);
                float2 tf = funpack2(t);
                __half2 hh = __floats2half2_rn(tf.x, tf.y);
                h[j] = reinterpret_cast<unsigned&>(hh);
            }
            size_t uoff = (((size_t)b * N_N + n) * N_C + c) * N_E + e_base;
            *reinterpret_cast<uint4*>(&g_u[uoff]) = make_uint4(h[0], h[1], h[2], h[3]);
        }
        __syncthreads();
    }

    #pragma unroll
    for (int i = 0; i < 4; i++) {
        int b = bq * 4 + i;
        ull* dst = reinterpret_cast<ull*>(
            &g_partials[(size_t)nb * SBCE + ((size_t)b * N_C + c) * N_E + e_base]);
        *reinterpret_cast<ulonglong2*>(dst)     = make_ulonglong2(sacc[i][0], sacc[i][1]);
        *reinterpret_cast<ulonglong2*>(dst + 2) = make_ulonglong2(sacc[i][2], sacc[i][3]);
    }
}

// ---------------------------------------------------------------------------
// Kernel B (r15 proven, 244us config): logits = u.vsum, softmax_c, s += coup*u.
// Unroll-2 (2 n per barrier, parity wsum), pair-prefetch distance 1.
// ---------------------------------------------------------------------------
__global__ __launch_bounds__(256, 4)
void capsB()
{
    __shared__ __align__(16) float wsum[2][2][8];   // [parity][which n][warp]

    const int tid  = threadIdx.x;
    const int b    = blockIdx.x;
    const int nb   = blockIdx.y;
    const int ns   = (nb * N_N) / NPART;
    const int ne   = ((nb + 1) * N_N) / NPART;
    const int lane = tid & 31;
    const int wid  = tid >> 5;

    // vsum for this (c, 8e), packed f32x2
    ull vs2[4];
    {
        const float4* vp = reinterpret_cast<const float4*>(
            g_vsum + (size_t)b * (N_C * N_E) + tid * 8);
        float4 v0 = vp[0], v1 = vp[1];
        vs2[0] = fpack2(v0.x, v0.y);
        vs2[1] = fpack2(v0.z, v0.w);
        vs2[2] = fpack2(v1.x, v1.y);
        vs2[3] = fpack2(v1.z, v1.w);
    }
    ull sacc2[4] = { 0ull, 0ull, 0ull, 0ull };

    const uint4* __restrict__ up = reinterpret_cast<const uint4*>(
        g_u + (size_t)b * N_N * (N_C * N_E) + tid * 8);

    const int cnt    = ne - ns;          // 55 or 56
    const int npairs = cnt >> 1;

    uint4 v0 = up[(size_t)ns * U_ROW_U4];
    uint4 v1 = up[(size_t)(ns + 1) * U_ROW_U4];

    int p = 0;
    int n = ns;
    for (int it = 0; it < npairs; it++, n += 2, p ^= 1) {
        uint4 v2 = up[(size_t)(n + 2) * U_ROW_U4];   // next pair (padded tail)
        uint4 v3 = up[(size_t)(n + 3) * U_ROW_U4];

        ull a0 = h2f2(v0.x), a1 = h2f2(v0.y), a2 = h2f2(v0.z), a3 = h2f2(v0.w);
        ull b0 = h2f2(v1.x), b1 = h2f2(v1.y), b2 = h2f2(v1.z), b3 = h2f2(v1.w);

        ull accA = ffma2(a0, vs2[0], 0ull);
        ull accB = ffma2(b0, vs2[0], 0ull);
        accA = ffma2(a1, vs2[1], accA);
        accB = ffma2(b1, vs2[1], accB);
        accA = ffma2(a2, vs2[2], accA);
        accB = ffma2(b2, vs2[2], accB);
        accA = ffma2(a3, vs2[3], accA);
        accB = ffma2(b3, vs2[3], accB);
        float2 fA = funpack2(accA);
        float2 fB = funpack2(accB);
        float lpA = fA.x + fA.y;
        float lpB = fB.x + fB.y;
        lpA += __shfl_xor_sync(0xffffffffu, lpA, 1);
        lpB += __shfl_xor_sync(0xffffffffu, lpB, 1);
        lpA += __shfl_xor_sync(0xffffffffu, lpA, 2);
        lpB += __shfl_xor_sync(0xffffffffu, lpB, 2);

        float exA = __expf(lpA);
        float exB = __expf(lpB);
        float sA = exA, sB = exB;
        sA += __shfl_xor_sync(0xffffffffu, sA, 4);
        sB += __shfl_xor_sync(0xffffffffu, sB, 4);
        sA += __shfl_xor_sync(0xffffffffu, sA, 8);
        sB += __shfl_xor_sync(0xffffffffu, sB, 8);
        sA += __shfl_xor_sync(0xffffffffu, sA, 16);
        sB += __shfl_xor_sync(0xffffffffu, sB, 16);
        if (lane == 0) {
            wsum[p][0][wid] = sA;
            wsum[p][1][wid] = sB;
        }
        __syncthreads();

        const float4* wpA = reinterpret_cast<const float4*>(wsum[p][0]);
        const float4* wpB = reinterpret_cast<const float4*>(wsum[p][1]);
        float4 aA = wpA[0], bA = wpA[1];
        float4 aB = wpB[0], bB = wpB[1];
        float totA = ((aA.x + aA.y) + (aA.z + aA.w)) +
                     ((bA.x + bA.y) + (bA.z + bA.w));
        float totB = ((aB.x + aB.y) + (aB.z + aB.w)) +
                     ((bB.x + bB.y) + (bB.z + bB.w));
        float coupA = __fdividef(exA, totA);
        float coupB = __fdividef(exB, totB);

        ull cA = fpack2(coupA, coupA);
        ull cB = fpack2(coupB, coupB);
        sacc2[0] = ffma2(cA, a0, sacc2[0]);
        sacc2[1] = ffma2(cA, a1, sacc2[1]);
        sacc2[2] = ffma2(cA, a2, sacc2[2]);
        sacc2[3] = ffma2(cA, a3, sacc2[3]);
        sacc2[0] = ffma2(cB, b0, sacc2[0]);
        sacc2[1] = ffma2(cB, b1, sacc2[1]);
        sacc2[2] = ffma2(cB, b2, sacc2[2]);
        sacc2[3] = ffma2(cB, b3, sacc2[3]);

        v0 = v2; v1 = v3;
    }

    if (cnt & 1) {
        // tail n = ns + cnt - 1; its row already sits in v0
        ull a0 = h2f2(v0.x), a1 = h2f2(v0.y), a2 = h2f2(v0.z), a3 = h2f2(v0.w);
        ull acc = ffma2(a0, vs2[0], 0ull);
        acc = ffma2(a1, vs2[1], acc);
        acc = ffma2(a2, vs2[2], acc);
        acc = ffma2(a3, vs2[3], acc);
        float2 f = funpack2(acc);
        float lp = f.x + f.y;
        lp += __shfl_xor_sync(0xffffffffu, lp, 1);
        lp += __shfl_xor_sync(0xffffffffu, lp, 2);
        float ex = __expf(lp);
        float s = ex;
        s += __shfl_xor_sync(0xffffffffu, s, 4);
        s += __shfl_xor_sync(0xffffffffu, s, 8);
        s += __shfl_xor_sync(0xffffffffu, s, 16);
        if (lane == 0) wsum[p][0][wid] = s;
        __syncthreads();
        const float4* wp = reinterpret_cast<const float4*>(wsum[p][0]);
        float4 wa = wp[0], wb = wp[1];
        float tot = ((wa.x + wa.y) + (wa.z + wa.w)) +
                    ((wb.x + wb.y) + (wb.z + wb.w));
        float coup = __fdividef(ex, tot);
        ull c2 = fpack2(coup, coup);
        sacc2[0] = ffma2(c2, a0, sacc2[0]);
        sacc2[1] = ffma2(c2, a1, sacc2[1]);
        sacc2[2] = ffma2(c2, a2, sacc2[2]);
        sacc2[3] = ffma2(c2, a3, sacc2[3]);
    }

    // write partials (32B contiguous per thread)
    ull* dst = reinterpret_cast<ull*>(
        &g_partials[(size_t)nb * SBCE + (size_t)b * (N_C * N_E) + tid * 8]);
    *reinterpret_cast<ulonglong2*>(dst)     = make_ulonglong2(sacc2[0], sacc2[1]);
    *reinterpret_cast<ulonglong2*>(dst + 2) = make_ulonglong2(sacc2[2], sacc2[3]);
}

// ---------------------------------------------------------------------------
// reduce partials + squash.  512 blocks x 128 threads (4 warps); warp = one
// (b,c) capsule, lane = e.  Same per-element arithmetic & order as before.
// ---------------------------------------------------------------------------
__global__ __launch_bounds__(128, 8)
void reduce_squash(float scale, int overwrite, float* __restrict__ out)
{
    int idx0 = blockIdx.x * 128 + threadIdx.x;   // 0..65535 (= bc*32 + e)
    size_t idx = (size_t)idx0;
    float s = 0.0f;
    #pragma unroll
    for (int p = 0; p < NPART; p++)
        s += g_partials[(size_t)p * SBCE + idx];
    s *= scale;
    float nsq = s * s;
    #pragma unroll
    for (int m = 16; m >= 1; m >>= 1)
        nsq += __shfl_xor_sync(0xffffffffu, nsq, m);
    float sc = nsq / ((1.0f + nsq) * sqrtf(nsq + 1e-9f));
    float v = sc * s;
    if (overwrite) g_vsum[idx] = v;
    else           g_vsum[idx] += v;
    if (out) out[idx] = v;
}

// ---------------------------------------------------------------------------
extern "C" void kernel_launch(void* const* d_in, const int* in_sizes, int n_in,
                              void* d_out, int out_size)
{
    const float* x  = (const float*)d_in[0];
    const float* W  = (const float*)d_in[1];
    const float* Bv = (const float*)d_in[2];
    float* out = (float*)d_out;

    cudaFuncSetAttribute(capsA, cudaFuncAttributeMaxDynamicSharedMemorySize,
                         CAPSA_SMEM_BYTES);

    dim3 gA(8, NPART);
    dim3 gB(N_B, NPART);

    capsA<<<gA, 256, CAPSA_SMEM_BYTES>>>(x, W, Bv);
    reduce_squash<<<512, 128>>>(1.0f / 64.0f, 1, nullptr);   // v1 -> vsum
    capsB<<<gB, 256>>>();
    reduce_squash<<<512, 128>>>(1.0f, 0, nullptr);           // vsum += v2
    capsB<<<gB, 256>>>();
    reduce_squash<<<512, 128>>>(1.0f, 0, out);
}